// round 16
// baseline (speedup 1.0000x reference)
#include <cuda_runtime.h>
#include <cuda_fp16.h>
#include <cstdint>

// Problem constants
#define BB    2
#define NSEQ  2048
#define EE    768
#define HH    12
#define DD    64
#define GG    16
#define CC    128
#define NCH   (NSEQ / CC)         // 16
#define BHH   (BB * HH)           // 24
#define MTOT  (BB * NSEQ)         // 4096

// ---------------- device scratch ----------------
__device__ float g_t16[MTOT * GG];
__device__ float g_T[BHH * NCH * DD * DD];
__device__ float g_S[BHH * NCH * DD * DD];

__device__ __half g_y16[MTOT * EE];     // pre-LN (fp16)
__device__ __half g_attn16[MTOT * EE];  // intra-chunk output (fp16)
__device__ __half g_xh[MTOT * EE];
__device__ __half g_ah[MTOT * EE];
__device__ __half g_wth[4 * EE * EE];   // transposed [n][k]

__device__ __half g_q16[MTOT * EE];
__device__ __half g_k16[MTOT * EE];
__device__ __half g_v16[MTOT * EE];

// ======================= helpers ==========================
__device__ __forceinline__ uint32_t smem_u32(const void* p) {
    uint32_t a;
    asm("{ .reg .u64 t; cvta.to.shared.u64 t, %1; cvt.u32.u64 %0, t; }"
        : "=r"(a) : "l"(p));
    return a;
}
__device__ __forceinline__ void cp_async16(uint32_t s, const void* g) {
    asm volatile("cp.async.cg.shared.global [%0], [%1], 16;" :: "r"(s), "l"(g));
}
__device__ __forceinline__ void cp_commit() {
    asm volatile("cp.async.commit_group;");
}
template <int N>
__device__ __forceinline__ void cp_wait() {
    asm volatile("cp.async.wait_group %0;" :: "n"(N));
}
__device__ __forceinline__ void ldsm4(uint32_t& r0, uint32_t& r1, uint32_t& r2,
                                      uint32_t& r3, uint32_t a) {
    asm volatile("ldmatrix.sync.aligned.m8n8.x4.shared.b16 {%0,%1,%2,%3}, [%4];"
                 : "=r"(r0), "=r"(r1), "=r"(r2), "=r"(r3) : "r"(a));
}
__device__ __forceinline__ void ldsm2(uint32_t& r0, uint32_t& r1, uint32_t a) {
    asm volatile("ldmatrix.sync.aligned.m8n8.x2.shared.b16 {%0,%1}, [%2];"
                 : "=r"(r0), "=r"(r1) : "r"(a));
}
__device__ __forceinline__ void ldsm4t(uint32_t& r0, uint32_t& r1, uint32_t& r2,
                                       uint32_t& r3, uint32_t a) {
    asm volatile("ldmatrix.sync.aligned.m8n8.x4.trans.shared.b16 {%0,%1,%2,%3}, [%4];"
                 : "=r"(r0), "=r"(r1), "=r"(r2), "=r"(r3) : "r"(a));
}
__device__ __forceinline__ void ldsm2t(uint32_t& r0, uint32_t& r1, uint32_t a) {
    asm volatile("ldmatrix.sync.aligned.m8n8.x2.trans.shared.b16 {%0,%1}, [%2];"
                 : "=r"(r0), "=r"(r1) : "r"(a));
}
__device__ __forceinline__ void mma_fp16(float* c, const uint32_t* a,
                                         const uint32_t* b) {
    asm volatile(
        "mma.sync.aligned.m16n8k16.row.col.f32.f16.f16.f32 "
        "{%0,%1,%2,%3}, {%4,%5,%6,%7}, {%8,%9}, {%0,%1,%2,%3};"
        : "+f"(c[0]), "+f"(c[1]), "+f"(c[2]), "+f"(c[3])
        : "r"(a[0]), "r"(a[1]), "r"(a[2]), "r"(a[3]), "r"(b[0]), "r"(b[1]));
}
__device__ __forceinline__ uint32_t pack2h(float a, float b) {
    __half ha = __float2half(a), hb = __float2half(b);
    return (uint32_t)*(uint16_t*)&ha | ((uint32_t)*(uint16_t*)&hb << 16);
}
// 64B-row swizzle (PROVEN conflict-free)
__device__ __forceinline__ uint32_t swz64(int r, int cbyte) {
    return (uint32_t)(r * 64 + (cbyte ^ (((r >> 1) & 3) << 4)));
}

// ======================= fused prep (+ gate GEMM) ========================
// blocks [0,3072): x -> fp16; [3072,5376): W transpose+fp16;
// [5376,5408): gate GEMM t16 = x @ Wg1 (reads fp32 inputs directly)
#define G1RB 776
__global__ __launch_bounds__(256) void prep_k(const float* __restrict__ x,
                                              const float* __restrict__ Wq,
                                              const float* __restrict__ Wk,
                                              const float* __restrict__ Wv,
                                              const float* __restrict__ Wo,
                                              const float* __restrict__ Wg1) {
    int bid = blockIdx.x;
    if (bid < 3072) {
        size_t i = ((size_t)bid * 256 + threadIdx.x) * 4;
        float4 v = *(const float4*)(x + i);
        __align__(8) __half h[4];
        h[0] = __float2half(v.x);
        h[1] = __float2half(v.y);
        h[2] = __float2half(v.z);
        h[3] = __float2half(v.w);
        *(uint2*)(g_xh + i) = *(uint2*)h;
    } else if (bid < 5376) {
        int rem = bid - 3072;
        int z = rem / 576, r2 = rem % 576;
        int bxb = (r2 % 24) * 32, byb = (r2 / 24) * 32;
        const float* W = (z == 0) ? Wq : (z == 1) ? Wk : (z == 2) ? Wv : Wo;
        __shared__ float t[32][33];
        int tx = threadIdx.x & 31, ty0 = threadIdx.x >> 5;
#pragma unroll
        for (int r = 0; r < 4; r++) {
            int ty = ty0 + r * 8;
            t[ty][tx] = W[(size_t)(byb + ty) * EE + bxb + tx];
        }
        __syncthreads();
        size_t base = (size_t)z * EE * EE;
#pragma unroll
        for (int r = 0; r < 4; r++) {
            int ty = ty0 + r * 8;
            g_wth[base + (size_t)(bxb + ty) * EE + byb + tx] = __float2half(t[tx][ty]);
        }
    } else {
        // gate GEMM: 32 blocks x 128 rows
        extern __shared__ __half sg[];
        __half* Bh = sg;               // [16][776]
        __half* Ahs = sg + 12416;      // [128][72]
        uint32_t sbase = smem_u32(sg);
        int tid = threadIdx.x, wid = tid >> 5, lane = tid & 31;
        int bm = (bid - 5376) * 128;

        for (int i = tid; i < GG * EE; i += 256) {
            int n = i / EE, k = i % EE;
            Bh[n * G1RB + k] = __float2half(Wg1[k * GG + n]);
        }

        float acc[2][4];
#pragma unroll
        for (int j = 0; j < 2; j++)
#pragma unroll
            for (int e = 0; e < 4; e++) acc[j][e] = 0.f;

        int a_r = lane & 15, a_k = (lane >> 4) << 3;
        int b_r = lane & 7, b_k = ((lane >> 3) & 1) << 3;

        for (int kt = 0; kt < 12; kt++) {
            __syncthreads();
            for (int i = tid; i < 2048; i += 256) {
                int p = i >> 4, c4 = (i & 15) * 4;
                float4 xv = *(const float4*)(x + (size_t)(bm + p) * EE + kt * 64 + c4);
                uint2 hx;
                hx.x = pack2h(xv.x, xv.y);
                hx.y = pack2h(xv.z, xv.w);
                *(uint2*)(Ahs + p * 72 + c4) = hx;
            }
            __syncthreads();
#pragma unroll
            for (int ks = 0; ks < 4; ks++) {
                int kk = ks * 16;
                uint32_t ah[4];
                int row = wid * 16 + a_r;
                uint32_t offa = (uint32_t)(12416 + row * 72 + kk + a_k) * 2;
                ldsm4(ah[0], ah[1], ah[2], ah[3], sbase + offa);
#pragma unroll
                for (int jn = 0; jn < 2; jn++) {
                    int nrow = jn * 8 + b_r;
                    uint32_t offb = (uint32_t)(nrow * G1RB + kt * 64 + kk + b_k) * 2;
                    uint32_t bh[2];
                    ldsm2(bh[0], bh[1], sbase + offb);
                    mma_fp16(acc[jn], ah, bh);
                }
            }
        }
        int er = lane >> 2, ec = (lane & 3) * 2;
#pragma unroll
        for (int jn = 0; jn < 2; jn++) {
            int row = bm + wid * 16 + er;
            int col = jn * 8 + ec;
            *(float2*)(g_t16 + (size_t)row * GG + col) =
                make_float2(acc[jn][0], acc[jn][1]);
            *(float2*)(g_t16 + (size_t)(row + 8) * GG + col) =
                make_float2(acc[jn][2], acc[jn][3]);
        }
    }
}

// ======================= single-fp16 mma.sync GEMM (QKV, 128x128) ========
#define MMSTG 32768
#define MM_A 0
#define MM_B 16384

__global__ __launch_bounds__(256, 2) void mm_tc() {
    extern __shared__ char smem[];
    uint32_t sb = smem_u32(smem);

    int tid = threadIdx.x;
    int wid = tid >> 5, lane = tid & 31;
    int wm = wid & 1, wn = wid >> 1;

    int z = blockIdx.z;
    const __half* Ah = g_xh;
    const __half* Wh = g_wth + (size_t)z * EE * EE;
    __half* C1 = (z == 0) ? g_q16 : (z == 1) ? g_k16 : g_v16;
    int bm = blockIdx.y * 128, bn = blockIdx.x * 128;

    float acc[4][4][4];
#pragma unroll
    for (int i = 0; i < 4; i++)
#pragma unroll
        for (int j = 0; j < 4; j++)
#pragma unroll
            for (int e = 0; e < 4; e++) acc[i][j][e] = 0.f;

    int lr0 = tid >> 2;
    int lcb = (tid & 3) * 16;
    int lce = (tid & 3) * 8;

    auto issue = [&](int kt, int stg) {
        int k0 = kt * 64;
        uint32_t st = sb + (uint32_t)stg * MMSTG;
#pragma unroll
        for (int hh = 0; hh < 2; hh++) {
            uint32_t hb = (uint32_t)hh * 8192u;
            int ke = k0 + hh * 32 + lce;
#pragma unroll
            for (int rr = 0; rr < 2; rr++) {
                int r = lr0 + rr * 64;
                uint32_t so = swz64(r, lcb);
                cp_async16(st + MM_A + hb + so, Ah + (size_t)(bm + r) * EE + ke);
                cp_async16(st + MM_B + hb + so, Wh + (size_t)(bn + r) * EE + ke);
            }
        }
        cp_commit();
    };

    int a_r = lane & 15;
    int a_kb = ((lane >> 4) & 1) << 4;
    int bg = lane >> 3;
    int b_r = lane & 7;
    int b_jn = bg >> 1;
    int b_kb = (bg & 1) << 4;

    issue(0, 0);
    issue(1, 1);
    int stg = 0;
    for (int kt = 0; kt < 12; kt++) {
        if (kt < 11) cp_wait<1>(); else cp_wait<0>();
        __syncthreads();
        if (kt < 10) {
            int ns = stg + 2;
            if (ns >= 3) ns -= 3;
            issue(kt + 2, ns);
        }
        uint32_t st = sb + (uint32_t)stg * MMSTG;
#pragma unroll
        for (int hh = 0; hh < 2; hh++) {
            uint32_t hb = (uint32_t)hh * 8192u;
#pragma unroll
            for (int ks = 0; ks < 2; ks++) {
                int kb = ks * 32;
                uint32_t bh[4][2];
#pragma unroll
                for (int jp = 0; jp < 2; jp++) {
                    int nrow = wn * 32 + (jp * 2 + b_jn) * 8 + b_r;
                    uint32_t off = swz64(nrow, kb + b_kb);
                    ldsm4(bh[jp * 2][0], bh[jp * 2][1], bh[jp * 2 + 1][0],
                          bh[jp * 2 + 1][1], st + MM_B + hb + off);
                }
#pragma unroll
                for (int im = 0; im < 4; im++) {
                    int row = wm * 64 + im * 16 + a_r;
                    uint32_t off = swz64(row, kb + a_kb);
                    uint32_t ah[4];
                    ldsm4(ah[0], ah[1], ah[2], ah[3], st + MM_A + hb + off);
#pragma unroll
                    for (int jn = 0; jn < 4; jn++)
                        mma_fp16(acc[im][jn], ah, bh[jn]);
                }
            }
        }
        stg++;
        if (stg == 3) stg = 0;
    }

    int er = lane >> 2, ec = (lane & 3) * 2;
#pragma unroll
    for (int im = 0; im < 4; im++) {
#pragma unroll
        for (int jn = 0; jn < 4; jn++) {
            int row = bm + wm * 64 + im * 16 + er;
            int col = bn + wn * 32 + jn * 8 + ec;
            float v0 = acc[im][jn][0], v1 = acc[im][jn][1];
            float v2 = acc[im][jn][2], v3 = acc[im][jn][3];
            v0 = v0 / (1.f + __expf(-v0));
            v1 = v1 / (1.f + __expf(-v1));
            v2 = v2 / (1.f + __expf(-v2));
            v3 = v3 / (1.f + __expf(-v3));
            *(uint32_t*)(C1 + (size_t)row * EE + col) = pack2h(v0, v1);
            *(uint32_t*)(C1 + (size_t)(row + 8) * EE + col) = pack2h(v2, v3);
        }
    }
}

// ======================= mm_tc2: Wo GEMM, 64x128 tiles ===================
#define M2STG 24576

__global__ __launch_bounds__(256, 2) void mm_tc2() {
    extern __shared__ char smem[];
    uint32_t sb = smem_u32(smem);

    int tid = threadIdx.x;
    int wid = tid >> 5, lane = tid & 31;
    int wm = wid & 1, wn = wid >> 1;

    const __half* Ah = g_ah;
    const __half* Wh = g_wth + (size_t)3 * EE * EE;
    int bm = blockIdx.y * 64, bn = blockIdx.x * 128;

    float acc[2][4][4];
#pragma unroll
    for (int i = 0; i < 2; i++)
#pragma unroll
        for (int j = 0; j < 4; j++)
#pragma unroll
            for (int e = 0; e < 4; e++) acc[i][j][e] = 0.f;

    int lr0 = tid >> 2;
    int lcb = (tid & 3) * 16;
    int lce = (tid & 3) * 8;

    auto issue = [&](int kt, int stg) {
        int k0 = kt * 64;
        uint32_t st = sb + (uint32_t)stg * M2STG;
#pragma unroll
        for (int hh = 0; hh < 2; hh++) {
            int ke = k0 + hh * 32 + lce;
            uint32_t soA = swz64(lr0, lcb);
            cp_async16(st + (uint32_t)hh * 4096u + soA,
                       Ah + (size_t)(bm + lr0) * EE + ke);
#pragma unroll
            for (int rr = 0; rr < 2; rr++) {
                int r = lr0 + rr * 64;
                cp_async16(st + 8192u + (uint32_t)hh * 8192u + swz64(r, lcb),
                           Wh + (size_t)(bn + r) * EE + ke);
            }
        }
        cp_commit();
    };

    int a_r = lane & 15;
    int a_kb = ((lane >> 4) & 1) << 4;
    int bg = lane >> 3;
    int b_r = lane & 7;
    int b_jn = bg >> 1;
    int b_kb = (bg & 1) << 4;

    issue(0, 0);
    issue(1, 1);
    int stg = 0;
    for (int kt = 0; kt < 12; kt++) {
        if (kt < 11) cp_wait<1>(); else cp_wait<0>();
        __syncthreads();
        if (kt < 10) {
            int ns = stg + 2;
            if (ns >= 3) ns -= 3;
            issue(kt + 2, ns);
        }
        uint32_t st = sb + (uint32_t)stg * M2STG;
#pragma unroll
        for (int hh = 0; hh < 2; hh++) {
            uint32_t abase = st + (uint32_t)hh * 4096u;
            uint32_t bbase = st + 8192u + (uint32_t)hh * 8192u;
#pragma unroll
            for (int ks = 0; ks < 2; ks++) {
                int kb = ks * 32;
                uint32_t bh[4][2];
#pragma unroll
                for (int jp = 0; jp < 2; jp++) {
                    int nrow = wn * 32 + (jp * 2 + b_jn) * 8 + b_r;
                    ldsm4(bh[jp * 2][0], bh[jp * 2][1], bh[jp * 2 + 1][0],
                          bh[jp * 2 + 1][1], bbase + swz64(nrow, kb + b_kb));
                }
#pragma unroll
                for (int im = 0; im < 2; im++) {
                    int row = wm * 32 + im * 16 + a_r;
                    uint32_t ah[4];
                    ldsm4(ah[0], ah[1], ah[2], ah[3], abase + swz64(row, kb + a_kb));
#pragma unroll
                    for (int jn = 0; jn < 4; jn++)
                        mma_fp16(acc[im][jn], ah, bh[jn]);
                }
            }
        }
        stg++;
        if (stg == 3) stg = 0;
    }

    int er = lane >> 2, ec = (lane & 3) * 2;
#pragma unroll
    for (int im = 0; im < 2; im++)
#pragma unroll
        for (int jn = 0; jn < 4; jn++) {
            int row = bm + wm * 32 + im * 16 + er;
            int col = bn + wn * 32 + jn * 8 + ec;
            *(uint32_t*)(g_y16 + (size_t)row * EE + col) =
                pack2h(acc[im][jn][0], acc[im][jn][1]);
            *(uint32_t*)(g_y16 + (size_t)(row + 8) * EE + col) =
                pack2h(acc[im][jn][2], acc[im][jn][3]);
        }
}

// ======================= attention pass A (ldsm.trans, uint4 loads) ======
#define O_QH 0
#define O_KH 9216
#define O_VN 18432
#define O_KW 27648
#define O_AH 36864
#define O_END 54272
#define RQ 72
#define RT 136

__global__ __launch_bounds__(256, 2) void attn_intra_k(const float* __restrict__ lam) {
    extern __shared__ __align__(16) __half sh16[];
    float* dtab = (float*)(sh16 + O_END);
    uint32_t sbase = smem_u32(sh16);

    int tid = threadIdx.x, wid = tid >> 5, lane = tid & 31;
    int wm = wid & 1, wn = wid >> 1;
    int chunk = blockIdx.x, bh = blockIdx.y;
    int b = bh / HH, h = bh % HH;
    float lambda = lam[h];
    int n0 = chunk * CC;

    for (int i = tid; i <= CC; i += 256) dtab[i] = __expf(lambda * (float)i);

    for (int i = tid; i < 1024; i += 256) {
        int p = i >> 3, d8 = (i & 7) * 8;
        size_t gb = (size_t)(b * NSEQ + n0 + p) * EE + h * DD + d8;
        uint4 qv = *(const uint4*)(g_q16 + gb);
        uint4 kv = *(const uint4*)(g_k16 + gb);
        uint4 vv = *(const uint4*)(g_v16 + gb);
        *(uint4*)(sh16 + O_QH + p * RQ + d8) = qv;
        *(uint4*)(sh16 + O_KH + p * RQ + d8) = kv;
        *(uint4*)(sh16 + O_VN + p * RQ + d8) = vv;
        float w = __expf(lambda * (float)(CC - p));
        __half* kp = (__half*)&kv;
        __align__(16) __half kw[8];
#pragma unroll
        for (int e = 0; e < 8; e++)
            kw[e] = __float2half(__half2float(kp[e]) * w);
        *(uint4*)(sh16 + O_KW + p * RQ + d8) = *(uint4*)kw;
    }
    __syncthreads();

    int a_r = lane & 15, a_k = (lane >> 4) << 3;
    int b_r = lane & 7, b_k = ((lane >> 3) & 1) << 3;
    int er = lane >> 2, ec = (lane & 3) * 2;
    int tb_k = lane & 15;
    int ta_k = (lane & 7) | ((lane >> 4) << 3);
    int ta_m = ((lane >> 3) & 1) << 3;

    // ---- phase 1: S = Q @ K^T ----
    {
        float accS[4][4][4];
#pragma unroll
        for (int i = 0; i < 4; i++)
#pragma unroll
            for (int j = 0; j < 4; j++)
#pragma unroll
                for (int e = 0; e < 4; e++) accS[i][j][e] = 0.f;

#pragma unroll
        for (int ks = 0; ks < 4; ks++) {
            int kk = ks * 16;
            uint32_t kh[4][2];
#pragma unroll
            for (int jn = 0; jn < 4; jn++) {
                int nrow = wn * 32 + jn * 8 + b_r;
                ldsm2(kh[jn][0], kh[jn][1],
                      sbase + (uint32_t)(O_KH + nrow * RQ + kk + b_k) * 2);
            }
#pragma unroll
            for (int im = 0; im < 4; im++) {
                int row = wm * 64 + im * 16 + a_r;
                uint32_t qh[4];
                ldsm4(qh[0], qh[1], qh[2], qh[3],
                      sbase + (uint32_t)(O_QH + row * RQ + kk + a_k) * 2);
#pragma unroll
                for (int jn = 0; jn < 4; jn++)
                    mma_fp16(accS[im][jn], qh, kh[jn]);
            }
        }
#pragma unroll
        for (int im = 0; im < 4; im++)
#pragma unroll
            for (int jn = 0; jn < 4; jn++) {
                int p0 = wm * 64 + im * 16 + er;
                int j0 = wn * 32 + jn * 8 + ec;
                int dj = p0 - j0;
                float v0 = (dj >= 0)     ? accS[im][jn][0] * dtab[dj] : 0.f;
                float v1 = (dj - 1 >= 0) ? accS[im][jn][1] * dtab[dj - 1] : 0.f;
                float v2 = (dj + 8 >= 0) ? accS[im][jn][2] * dtab[dj + 8] : 0.f;
                float v3 = (dj + 7 >= 0) ? accS[im][jn][3] * dtab[dj + 7] : 0.f;
                *(uint32_t*)(sh16 + O_AH + p0 * RT + j0) = pack2h(v0, v1);
                *(uint32_t*)(sh16 + O_AH + (p0 + 8) * RT + j0) = pack2h(v2, v3);
            }
    }
    __syncthreads();

    // ---- phase 2: O = A @ V (V^T via ldsm2t) -> g_attn16 ----
    {
        float accO[4][2][4];
#pragma unroll
        for (int i = 0; i < 4; i++)
#pragma unroll
            for (int j = 0; j < 2; j++)
#pragma unroll
                for (int e = 0; e < 4; e++) accO[i][j][e] = 0.f;

#pragma unroll
        for (int ks = 0; ks < 8; ks++) {
            int kk = ks * 16;
            uint32_t vh[2][2];
#pragma unroll
            for (int jn = 0; jn < 2; jn++) {
                int ncol = wn * 16 + jn * 8;
                ldsm2t(vh[jn][0], vh[jn][1],
                       sbase + (uint32_t)(O_VN + (kk + tb_k) * RQ + ncol) * 2);
            }
#pragma unroll
            for (int im = 0; im < 4; im++) {
                int row = wm * 64 + im * 16 + a_r;
                uint32_t ah[4];
                ldsm4(ah[0], ah[1], ah[2], ah[3],
                      sbase + (uint32_t)(O_AH + row * RT + kk + a_k) * 2);
#pragma unroll
                for (int jn = 0; jn < 2; jn++)
                    mma_fp16(accO[im][jn], ah, vh[jn]);
            }
        }
#pragma unroll
        for (int im = 0; im < 4; im++)
#pragma unroll
            for (int jn = 0; jn < 2; jn++) {
                int p0 = wm * 64 + im * 16 + er;
                int col = wn * 16 + jn * 8 + ec;
                size_t gb = (size_t)(b * NSEQ + n0 + p0) * EE + h * DD + col;
                *(uint32_t*)(g_attn16 + gb) = pack2h(accO[im][jn][0], accO[im][jn][1]);
                *(uint32_t*)(g_attn16 + gb + (size_t)8 * EE) =
                    pack2h(accO[im][jn][2], accO[im][jn][3]);
            }
    }

    // ---- phase 3: T = Kw^T @ V ----
    {
        float accT[2][2][4];
#pragma unroll
        for (int i = 0; i < 2; i++)
#pragma unroll
            for (int j = 0; j < 2; j++)
#pragma unroll
                for (int e = 0; e < 4; e++) accT[i][j][e] = 0.f;

#pragma unroll
        for (int ks = 0; ks < 8; ks++) {
            int kk = ks * 16;
            uint32_t vh[2][2];
#pragma unroll
            for (int jn = 0; jn < 2; jn++) {
                int ncol = wn * 16 + jn * 8;
                ldsm2t(vh[jn][0], vh[jn][1],
                       sbase + (uint32_t)(O_VN + (kk + tb_k) * RQ + ncol) * 2);
            }
#pragma unroll
            for (int im = 0; im < 2; im++) {
                int mcol = wm * 32 + im * 16;
                uint32_t kwh[4];
                ldsm4t(kwh[0], kwh[1], kwh[2], kwh[3],
                       sbase + (uint32_t)(O_KW + (kk + ta_k) * RQ + mcol + ta_m) * 2);
#pragma unroll
                for (int jn = 0; jn < 2; jn++)
                    mma_fp16(accT[im][jn], kwh, vh[jn]);
            }
        }
        size_t tb = ((size_t)bh * NCH + chunk) * DD * DD;
#pragma unroll
        for (int im = 0; im < 2; im++)
#pragma unroll
            for (int jn = 0; jn < 2; jn++) {
                int dk = wm * 32 + im * 16 + er;
                int dv = wn * 16 + jn * 8 + ec;
                *(float2*)(g_T + tb + dk * DD + dv) =
                    make_float2(accT[im][jn][0], accT[im][jn][1]);
                *(float2*)(g_T + tb + (dk + 8) * DD + dv) =
                    make_float2(accT[im][jn][2], accT[im][jn][3]);
            }
    }
}

// ======================= pass B: chunk-state scan (full-chip) ============
__global__ __launch_bounds__(256) void scan_k(const float* __restrict__ lam) {
    int idx = blockIdx.x * 256 + threadIdx.x;
    int bh = idx >> 12;
    int e = idx & 4095;
    int h = bh % HH;
    float gamma = __expf(lam[h] * (float)CC);
    size_t base = (size_t)bh * NCH * DD * DD + e;
    float s = 0.f;
#pragma unroll
    for (int t = 0; t < NCH; t++) {
        g_S[base + t * DD * DD] = s;
        s = gamma * s + g_T[base + t * DD * DD];
    }
}

// ======================= pass C: inter (mma) + gate fuse + fp16 out ======
#define I_QE 0
#define I_ST 9216
#define I_END 13824

__global__ __launch_bounds__(256) void attn_inter_k(const float* __restrict__ lam,
                                                    const float* __restrict__ Wg2) {
    extern __shared__ __align__(16) __half si16[];
    float* fb = (float*)(si16 + I_END);
    float* t16s = fb;
    float* wg2s = fb + 2048;
    uint32_t sbase = smem_u32(si16);

    int tid = threadIdx.x, wid = tid >> 5, lane = tid & 31;
    int wm = wid & 1, wn = wid >> 1;
    int chunk = blockIdx.x, bh = blockIdx.y;
    int b = bh / HH, h = bh % HH;
    float lambda = lam[h];
    int n0 = chunk * CC;

    for (int i = tid; i < 1024; i += 256) {
        int p = i >> 3, d8 = (i & 7) * 8;
        size_t gb = (size_t)(b * NSEQ + n0 + p) * EE + h * DD + d8;
        uint4 qv = *(const uint4*)(g_q16 + gb);
        float w = __expf(lambda * (float)p);
        __half* qp = (__half*)&qv;
        __align__(16) __half qe[8];
#pragma unroll
        for (int e = 0; e < 8; e++)
            qe[e] = __float2half(__half2float(qp[e]) * w);
        *(uint4*)(si16 + I_QE + p * RQ + d8) = *(uint4*)qe;
    }
    size_t sbo = ((size_t)bh * NCH + chunk) * DD * DD;
    for (int i = tid; i < 1024; i += 256) {
        int dk = i >> 4, dv4 = (i & 15) * 4;
        float4 sv = *(const float4*)(g_S + sbo + dk * 64 + dv4);
        uint2 u;
        u.x = pack2h(sv.x, sv.y);
        u.y = pack2h(sv.z, sv.w);
        *(uint2*)(si16 + I_ST + dk * RQ + dv4) = u;
    }
    for (int i = tid; i < 512; i += 256)
        *(float4*)(t16s + i * 4) =
            *(const float4*)(g_t16 + (size_t)(b * NSEQ + n0) * GG + i * 4);
    for (int i = tid; i < 256; i += 256) {
        int g = i >> 4, c4 = (i & 15) * 4;
        *(float4*)(wg2s + g * 64 + c4) = *(const float4*)(Wg2 + g * EE + h * DD + c4);
    }
    __syncthreads();

    int a_r = lane & 15, a_k = (lane >> 4) << 3;
    int er = lane >> 2, ec = (lane & 3) * 2;
    int tb_k = lane & 15;

    float accO[4][2][4];
#pragma unroll
    for (int i = 0; i < 4; i++)
#pragma unroll
        for (int j = 0; j < 2; j++)
#pragma unroll
            for (int e = 0; e < 4; e++) accO[i][j][e] = 0.f;

#pragma unroll
    for (int ks = 0; ks < 4; ks++) {
        int kk = ks * 16;
        uint32_t shh[2][2];
#pragma unroll
        for (int jn = 0; jn < 2; jn++) {
            int ncol = wn * 16 + jn * 8;
            ldsm2t(shh[jn][0], shh[jn][1],
                   sbase + (uint32_t)(I_ST + (kk + tb_k) * RQ + ncol) * 2);
        }
#pragma unroll
        for (int im = 0; im < 4; im++) {
            int row = wm * 64 + im * 16 + a_r;
            uint32_t qh[4];
            ldsm4(qh[0], qh[1], qh[2], qh[3],
                  sbase + (uint32_t)(I_QE + row * RQ + kk + a_k) * 2);
#pragma unroll
            for (int jn = 0; jn < 2; jn++)
                mma_fp16(accO[im][jn], qh, shh[jn]);
        }
    }

#pragma unroll
    for (int im = 0; im < 4; im++)
#pragma unroll
        for (int jn = 0; jn < 2; jn++) {
            int p0 = wm * 64 + im * 16 + er;
            int col = wn * 16 + jn * 8 + ec;
#pragma unroll
            for (int rr = 0; rr < 2; rr++) {
                int p = p0 + rr * 8;
                size_t gb = (size_t)(b * NSEQ + n0 + p) * EE + h * DD + col;
                uint32_t aw = *(const uint32_t*)(g_attn16 + gb);
                __half* ap = (__half*)&aw;
                float s0 = 0.f, s1 = 0.f;
#pragma unroll
                for (int g = 0; g < 16; g++) {
                    float tv = t16s[p * 16 + g];
                    s0 += tv * wg2s[g * 64 + col];
                    s1 += tv * wg2s[g * 64 + col + 1];
                }
                float g0 = 1.f / (1.f + __expf(-s0));
                float g1 = 1.f / (1.f + __expf(-s1));
                float v0 = (__half2float(ap[0]) + accO[im][jn][rr * 2 + 0]) * g0;
                float v1 = (__half2float(ap[1]) + accO[im][jn][rr * 2 + 1]) * g1;
                *(uint32_t*)(g_ah + gb) = pack2h(v0, v1);
            }
        }
}

// ======================= LayerNorm (fp16 input) ==========================
__global__ __launch_bounds__(256) void ln_k(const float* __restrict__ w,
                                            const float* __restrict__ bias,
                                            float* __restrict__ out) {
    int row = blockIdx.x;
    int t = threadIdx.x;
    const __half* yr = g_y16 + (size_t)row * EE;
    float v0 = __half2float(yr[t]);
    float v1 = __half2float(yr[t + 256]);
    float v2 = __half2float(yr[t + 512]);

    __shared__ float red[32];
    float s = v0 + v1 + v2;
#pragma unroll
    for (int off = 16; off > 0; off >>= 1) s += __shfl_down_sync(0xffffffffu, s, off);
    if ((t & 31) == 0) red[t >> 5] = s;
    __syncthreads();
    if (t < 32) {
        float x = (t < 8) ? red[t] : 0.f;
#pragma unroll
        for (int off = 4; off > 0; off >>= 1) x += __shfl_down_sync(0xffffffffu, x, off);
        if (t == 0) red[0] = x;
    }
    __syncthreads();
    float mu = red[0] * (1.f / 768.f);
    __syncthreads();

    float d0 = v0 - mu, d1 = v1 - mu, d2 = v2 - mu;
    float s2 = d0 * d0 + d1 * d1 + d2 * d2;
#pragma unroll
    for (int off = 16; off > 0; off >>= 1) s2 += __shfl_down_sync(0xffffffffu, s2, off);
    if ((t & 31) == 0) red[t >> 5] = s2;
    __syncthreads();
    if (t < 32) {
        float x = (t < 8) ? red[t] : 0.f;
#pragma unroll
        for (int off = 4; off > 0; off >>= 1) x += __shfl_down_sync(0xffffffffu, x, off);
        if (t == 0) red[0] = x;
    }
    __syncthreads();
    float var = red[0] * (1.f / 768.f);
    float rs = rsqrtf(var + 1e-5f);

    size_t ob = (size_t)row * EE;
    out[ob + t]       = d0 * rs * w[t]       + bias[t];
    out[ob + t + 256] = d1 * rs * w[t + 256] + bias[t + 256];
    out[ob + t + 512] = d2 * rs * w[t + 512] + bias[t + 512];
}

// =========================================================================
extern "C" void kernel_launch(void* const* d_in, const int* in_sizes, int n_in,
                              void* d_out, int out_size) {
    (void)in_sizes; (void)n_in; (void)out_size;
    const float* x         = (const float*)d_in[0];
    const float* log_slope = (const float*)d_in[1];
    const float* Wq        = (const float*)d_in[2];
    const float* Wk        = (const float*)d_in[3];
    const float* Wv        = (const float*)d_in[4];
    const float* Wo        = (const float*)d_in[5];
    const float* Wg1       = (const float*)d_in[6];
    const float* Wg2       = (const float*)d_in[7];
    const float* ln_w      = (const float*)d_in[8];
    const float* ln_b      = (const float*)d_in[9];
    float* out = (float*)d_out;

    int smPrep = (12416 + 128 * 72) * 2;   // ~43.3 KB (gate-GEMM blocks)
    cudaFuncSetAttribute(prep_k, cudaFuncAttributeMaxDynamicSharedMemorySize, smPrep);
    int smMM = 3 * MMSTG;
    cudaFuncSetAttribute(mm_tc, cudaFuncAttributeMaxDynamicSharedMemorySize, smMM);
    int smM2 = 3 * M2STG;
    cudaFuncSetAttribute(mm_tc2, cudaFuncAttributeMaxDynamicSharedMemorySize, smM2);
    int smA = O_END * 2 + 132 * 4;
    cudaFuncSetAttribute(attn_intra_k, cudaFuncAttributeMaxDynamicSharedMemorySize, smA);
    int smC = I_END * 2 + (2048 + 1024) * 4;
    cudaFuncSetAttribute(attn_inter_k, cudaFuncAttributeMaxDynamicSharedMemorySize, smC);

    prep_k<<<5408, 256, smPrep>>>(x, Wq, Wk, Wv, Wo, Wg1);
    mm_tc<<<dim3(EE / 128, MTOT / 128, 3), 256, smMM>>>();
    attn_intra_k<<<dim3(NCH, BHH), 256, smA>>>(log_slope);
    scan_k<<<BHH * NCH * 16 * 16 / 256, 256>>>(log_slope);
    attn_inter_k<<<dim3(NCH, BHH), 256, smC>>>(log_slope, Wg2);
    mm_tc2<<<dim3(EE / 128, MTOT / 64, 1), 256, smM2>>>();
    ln_k<<<MTOT, 256>>>(ln_w, ln_b, out);
}

// round 17
// speedup vs baseline: 1.1180x; 1.1180x over previous
#include <cuda_runtime.h>
#include <cuda_fp16.h>
#include <cstdint>

// Problem constants
#define BB    2
#define NSEQ  2048
#define EE    768
#define HH    12
#define DD    64
#define GG    16
#define CC    128
#define NCH   (NSEQ / CC)         // 16
#define BHH   (BB * HH)           // 24
#define MTOT  (BB * NSEQ)         // 4096

// ---------------- device scratch ----------------
__device__ float g_t16[MTOT * GG];
__device__ float g_T[BHH * NCH * DD * DD];
__device__ float g_S[BHH * NCH * DD * DD];

__device__ __half g_y16[MTOT * EE];     // pre-LN (fp16)
__device__ __half g_attn16[MTOT * EE];  // intra-chunk output (fp16)
__device__ __half g_xh[MTOT * EE];
__device__ __half g_ah[MTOT * EE];
__device__ __half g_wth[4 * EE * EE];   // transposed [n][k]
__device__ __half g_g1th[GG * EE];      // Wg1 transposed [g][k]

__device__ __half g_q16[MTOT * EE];
__device__ __half g_k16[MTOT * EE];
__device__ __half g_v16[MTOT * EE];

// ======================= helpers ==========================
__device__ __forceinline__ uint32_t smem_u32(const void* p) {
    uint32_t a;
    asm("{ .reg .u64 t; cvta.to.shared.u64 t, %1; cvt.u32.u64 %0, t; }"
        : "=r"(a) : "l"(p));
    return a;
}
__device__ __forceinline__ void cp_async16(uint32_t s, const void* g) {
    asm volatile("cp.async.cg.shared.global [%0], [%1], 16;" :: "r"(s), "l"(g));
}
__device__ __forceinline__ void cp_commit() {
    asm volatile("cp.async.commit_group;");
}
template <int N>
__device__ __forceinline__ void cp_wait() {
    asm volatile("cp.async.wait_group %0;" :: "n"(N));
}
__device__ __forceinline__ void ldsm4(uint32_t& r0, uint32_t& r1, uint32_t& r2,
                                      uint32_t& r3, uint32_t a) {
    asm volatile("ldmatrix.sync.aligned.m8n8.x4.shared.b16 {%0,%1,%2,%3}, [%4];"
                 : "=r"(r0), "=r"(r1), "=r"(r2), "=r"(r3) : "r"(a));
}
__device__ __forceinline__ void ldsm2(uint32_t& r0, uint32_t& r1, uint32_t a) {
    asm volatile("ldmatrix.sync.aligned.m8n8.x2.shared.b16 {%0,%1}, [%2];"
                 : "=r"(r0), "=r"(r1) : "r"(a));
}
__device__ __forceinline__ void ldsm4t(uint32_t& r0, uint32_t& r1, uint32_t& r2,
                                       uint32_t& r3, uint32_t a) {
    asm volatile("ldmatrix.sync.aligned.m8n8.x4.trans.shared.b16 {%0,%1,%2,%3}, [%4];"
                 : "=r"(r0), "=r"(r1), "=r"(r2), "=r"(r3) : "r"(a));
}
__device__ __forceinline__ void ldsm2t(uint32_t& r0, uint32_t& r1, uint32_t a) {
    asm volatile("ldmatrix.sync.aligned.m8n8.x2.trans.shared.b16 {%0,%1}, [%2];"
                 : "=r"(r0), "=r"(r1) : "r"(a));
}
__device__ __forceinline__ void mma_fp16(float* c, const uint32_t* a,
                                         const uint32_t* b) {
    asm volatile(
        "mma.sync.aligned.m16n8k16.row.col.f32.f16.f16.f32 "
        "{%0,%1,%2,%3}, {%4,%5,%6,%7}, {%8,%9}, {%0,%1,%2,%3};"
        : "+f"(c[0]), "+f"(c[1]), "+f"(c[2]), "+f"(c[3])
        : "r"(a[0]), "r"(a[1]), "r"(a[2]), "r"(a[3]), "r"(b[0]), "r"(b[1]));
}
__device__ __forceinline__ uint32_t pack2h(float a, float b) {
    __half ha = __float2half(a), hb = __float2half(b);
    return (uint32_t)*(uint16_t*)&ha | ((uint32_t)*(uint16_t*)&hb << 16);
}
// 64B-row swizzle (PROVEN conflict-free)
__device__ __forceinline__ uint32_t swz64(int r, int cbyte) {
    return (uint32_t)(r * 64 + (cbyte ^ (((r >> 1) & 3) << 4)));
}

// ======================= fused prep (conversions only) ===================
// blocks [0,3072): x -> fp16; [3072,5376): W transpose+fp16; [5376,5424): Wg1
__global__ __launch_bounds__(256) void prep_k(const float* __restrict__ x,
                                              const float* __restrict__ Wq,
                                              const float* __restrict__ Wk,
                                              const float* __restrict__ Wv,
                                              const float* __restrict__ Wo,
                                              const float* __restrict__ Wg1) {
    int bid = blockIdx.x;
    if (bid < 3072) {
        size_t i = ((size_t)bid * 256 + threadIdx.x) * 4;
        float4 v = *(const float4*)(x + i);
        __align__(8) __half h[4];
        h[0] = __float2half(v.x);
        h[1] = __float2half(v.y);
        h[2] = __float2half(v.z);
        h[3] = __float2half(v.w);
        *(uint2*)(g_xh + i) = *(uint2*)h;
    } else if (bid < 5376) {
        int rem = bid - 3072;
        int z = rem / 576, r2 = rem % 576;
        int bxb = (r2 % 24) * 32, byb = (r2 / 24) * 32;
        const float* W = (z == 0) ? Wq : (z == 1) ? Wk : (z == 2) ? Wv : Wo;
        __shared__ float t[32][33];
        int tx = threadIdx.x & 31, ty0 = threadIdx.x >> 5;
#pragma unroll
        for (int r = 0; r < 4; r++) {
            int ty = ty0 + r * 8;
            t[ty][tx] = W[(size_t)(byb + ty) * EE + bxb + tx];
        }
        __syncthreads();
        size_t base = (size_t)z * EE * EE;
#pragma unroll
        for (int r = 0; r < 4; r++) {
            int ty = ty0 + r * 8;
            g_wth[base + (size_t)(bxb + ty) * EE + byb + tx] = __float2half(t[tx][ty]);
        }
    } else {
        int i = (bid - 5376) * 256 + threadIdx.x;
        int n = i / EE, k = i % EE;
        g_g1th[i] = __float2half(Wg1[k * GG + n]);
    }
}

// ======================= single-fp16 mma.sync GEMM (QKV, 128x128) ========
#define MMSTG 32768
#define MM_A 0
#define MM_B 16384

__global__ __launch_bounds__(256, 2) void mm_tc() {
    extern __shared__ char smem[];
    uint32_t sb = smem_u32(smem);

    int tid = threadIdx.x;
    int wid = tid >> 5, lane = tid & 31;
    int wm = wid & 1, wn = wid >> 1;

    int z = blockIdx.z;
    const __half* Ah = g_xh;
    const __half* Wh = g_wth + (size_t)z * EE * EE;
    __half* C1 = (z == 0) ? g_q16 : (z == 1) ? g_k16 : g_v16;
    int bm = blockIdx.y * 128, bn = blockIdx.x * 128;

    float acc[4][4][4];
#pragma unroll
    for (int i = 0; i < 4; i++)
#pragma unroll
        for (int j = 0; j < 4; j++)
#pragma unroll
            for (int e = 0; e < 4; e++) acc[i][j][e] = 0.f;

    int lr0 = tid >> 2;
    int lcb = (tid & 3) * 16;
    int lce = (tid & 3) * 8;

    auto issue = [&](int kt, int stg) {
        int k0 = kt * 64;
        uint32_t st = sb + (uint32_t)stg * MMSTG;
#pragma unroll
        for (int hh = 0; hh < 2; hh++) {
            uint32_t hb = (uint32_t)hh * 8192u;
            int ke = k0 + hh * 32 + lce;
#pragma unroll
            for (int rr = 0; rr < 2; rr++) {
                int r = lr0 + rr * 64;
                uint32_t so = swz64(r, lcb);
                cp_async16(st + MM_A + hb + so, Ah + (size_t)(bm + r) * EE + ke);
                cp_async16(st + MM_B + hb + so, Wh + (size_t)(bn + r) * EE + ke);
            }
        }
        cp_commit();
    };

    int a_r = lane & 15;
    int a_kb = ((lane >> 4) & 1) << 4;
    int bg = lane >> 3;
    int b_r = lane & 7;
    int b_jn = bg >> 1;
    int b_kb = (bg & 1) << 4;

    issue(0, 0);
    issue(1, 1);
    int stg = 0;
    for (int kt = 0; kt < 12; kt++) {
        if (kt < 11) cp_wait<1>(); else cp_wait<0>();
        __syncthreads();
        if (kt < 10) {
            int ns = stg + 2;
            if (ns >= 3) ns -= 3;
            issue(kt + 2, ns);
        }
        uint32_t st = sb + (uint32_t)stg * MMSTG;
#pragma unroll
        for (int hh = 0; hh < 2; hh++) {
            uint32_t hb = (uint32_t)hh * 8192u;
#pragma unroll
            for (int ks = 0; ks < 2; ks++) {
                int kb = ks * 32;
                uint32_t bh[4][2];
#pragma unroll
                for (int jp = 0; jp < 2; jp++) {
                    int nrow = wn * 32 + (jp * 2 + b_jn) * 8 + b_r;
                    uint32_t off = swz64(nrow, kb + b_kb);
                    ldsm4(bh[jp * 2][0], bh[jp * 2][1], bh[jp * 2 + 1][0],
                          bh[jp * 2 + 1][1], st + MM_B + hb + off);
                }
#pragma unroll
                for (int im = 0; im < 4; im++) {
                    int row = wm * 64 + im * 16 + a_r;
                    uint32_t off = swz64(row, kb + a_kb);
                    uint32_t ah[4];
                    ldsm4(ah[0], ah[1], ah[2], ah[3], st + MM_A + hb + off);
#pragma unroll
                    for (int jn = 0; jn < 4; jn++)
                        mma_fp16(acc[im][jn], ah, bh[jn]);
                }
            }
        }
        stg++;
        if (stg == 3) stg = 0;
    }

    int er = lane >> 2, ec = (lane & 3) * 2;
#pragma unroll
    for (int im = 0; im < 4; im++) {
#pragma unroll
        for (int jn = 0; jn < 4; jn++) {
            int row = bm + wm * 64 + im * 16 + er;
            int col = bn + wn * 32 + jn * 8 + ec;
            float v0 = acc[im][jn][0], v1 = acc[im][jn][1];
            float v2 = acc[im][jn][2], v3 = acc[im][jn][3];
            v0 = v0 / (1.f + __expf(-v0));
            v1 = v1 / (1.f + __expf(-v1));
            v2 = v2 / (1.f + __expf(-v2));
            v3 = v3 / (1.f + __expf(-v3));
            *(uint32_t*)(C1 + (size_t)row * EE + col) = pack2h(v0, v1);
            *(uint32_t*)(C1 + (size_t)(row + 8) * EE + col) = pack2h(v2, v3);
        }
    }
}

// ======================= mm_tc2: Wo GEMM, 64x128 tiles ===================
#define M2STG 24576

__global__ __launch_bounds__(256, 2) void mm_tc2() {
    extern __shared__ char smem[];
    uint32_t sb = smem_u32(smem);

    int tid = threadIdx.x;
    int wid = tid >> 5, lane = tid & 31;
    int wm = wid & 1, wn = wid >> 1;

    const __half* Ah = g_ah;
    const __half* Wh = g_wth + (size_t)3 * EE * EE;
    int bm = blockIdx.y * 64, bn = blockIdx.x * 128;

    float acc[2][4][4];
#pragma unroll
    for (int i = 0; i < 2; i++)
#pragma unroll
        for (int j = 0; j < 4; j++)
#pragma unroll
            for (int e = 0; e < 4; e++) acc[i][j][e] = 0.f;

    int lr0 = tid >> 2;
    int lcb = (tid & 3) * 16;
    int lce = (tid & 3) * 8;

    auto issue = [&](int kt, int stg) {
        int k0 = kt * 64;
        uint32_t st = sb + (uint32_t)stg * M2STG;
#pragma unroll
        for (int hh = 0; hh < 2; hh++) {
            int ke = k0 + hh * 32 + lce;
            uint32_t soA = swz64(lr0, lcb);
            cp_async16(st + (uint32_t)hh * 4096u + soA,
                       Ah + (size_t)(bm + lr0) * EE + ke);
#pragma unroll
            for (int rr = 0; rr < 2; rr++) {
                int r = lr0 + rr * 64;
                cp_async16(st + 8192u + (uint32_t)hh * 8192u + swz64(r, lcb),
                           Wh + (size_t)(bn + r) * EE + ke);
            }
        }
        cp_commit();
    };

    int a_r = lane & 15;
    int a_kb = ((lane >> 4) & 1) << 4;
    int bg = lane >> 3;
    int b_r = lane & 7;
    int b_jn = bg >> 1;
    int b_kb = (bg & 1) << 4;

    issue(0, 0);
    issue(1, 1);
    int stg = 0;
    for (int kt = 0; kt < 12; kt++) {
        if (kt < 11) cp_wait<1>(); else cp_wait<0>();
        __syncthreads();
        if (kt < 10) {
            int ns = stg + 2;
            if (ns >= 3) ns -= 3;
            issue(kt + 2, ns);
        }
        uint32_t st = sb + (uint32_t)stg * M2STG;
#pragma unroll
        for (int hh = 0; hh < 2; hh++) {
            uint32_t abase = st + (uint32_t)hh * 4096u;
            uint32_t bbase = st + 8192u + (uint32_t)hh * 8192u;
#pragma unroll
            for (int ks = 0; ks < 2; ks++) {
                int kb = ks * 32;
                uint32_t bh[4][2];
#pragma unroll
                for (int jp = 0; jp < 2; jp++) {
                    int nrow = wn * 32 + (jp * 2 + b_jn) * 8 + b_r;
                    ldsm4(bh[jp * 2][0], bh[jp * 2][1], bh[jp * 2 + 1][0],
                          bh[jp * 2 + 1][1], bbase + swz64(nrow, kb + b_kb));
                }
#pragma unroll
                for (int im = 0; im < 2; im++) {
                    int row = wm * 32 + im * 16 + a_r;
                    uint32_t ah[4];
                    ldsm4(ah[0], ah[1], ah[2], ah[3], abase + swz64(row, kb + a_kb));
#pragma unroll
                    for (int jn = 0; jn < 4; jn++)
                        mma_fp16(acc[im][jn], ah, bh[jn]);
                }
            }
        }
        stg++;
        if (stg == 3) stg = 0;
    }

    int er = lane >> 2, ec = (lane & 3) * 2;
#pragma unroll
    for (int im = 0; im < 2; im++)
#pragma unroll
        for (int jn = 0; jn < 4; jn++) {
            int row = bm + wm * 32 + im * 16 + er;
            int col = bn + wn * 32 + jn * 8 + ec;
            *(uint32_t*)(g_y16 + (size_t)row * EE + col) =
                pack2h(acc[im][jn][0], acc[im][jn][1]);
            *(uint32_t*)(g_y16 + (size_t)(row + 8) * EE + col) =
                pack2h(acc[im][jn][2], acc[im][jn][3]);
        }
}

// ======================= mm_g1: 128 blocks x 64 threads ==================
#define G1RB 776
__global__ __launch_bounds__(64) void mm_g1() {
    extern __shared__ __half sg[];
    __half* Bh = sg;                 // [16][776]
    __half* Ahs = sg + 12416;        // [32][72]
    uint32_t sbase = smem_u32(sg);

    int tid = threadIdx.x, wid = tid >> 5, lane = tid & 31;
    int bm = blockIdx.x * 32;

    for (int i = tid; i < 16 * 96; i += 64) {
        int r = i / 96, c8 = (i % 96) * 8;
        *(uint4*)(Bh + r * G1RB + c8) = *(const uint4*)(g_g1th + r * EE + c8);
    }

    float acc[2][4];
#pragma unroll
    for (int j = 0; j < 2; j++)
#pragma unroll
        for (int e = 0; e < 4; e++) acc[j][e] = 0.f;

    int a_r = lane & 15, a_k = (lane >> 4) << 3;
    int b_r = lane & 7, b_k = ((lane >> 3) & 1) << 3;

    for (int kt = 0; kt < 12; kt++) {
        __syncthreads();
        for (int i = tid; i < 256; i += 64) {
            int p = i >> 3, c = i & 7;
            size_t go = (size_t)(bm + p) * EE + kt * 64 + c * 8;
            *(uint4*)(Ahs + p * 72 + c * 8) = *(const uint4*)(g_xh + go);
        }
        __syncthreads();
#pragma unroll
        for (int ks = 0; ks < 4; ks++) {
            int kk = ks * 16;
            uint32_t ah[4];
            int row = wid * 16 + a_r;
            uint32_t offa = (uint32_t)(12416 + row * 72 + kk + a_k) * 2;
            ldsm4(ah[0], ah[1], ah[2], ah[3], sbase + offa);
#pragma unroll
            for (int jn = 0; jn < 2; jn++) {
                int nrow = jn * 8 + b_r;
                uint32_t offb = (uint32_t)(nrow * G1RB + kt * 64 + kk + b_k) * 2;
                uint32_t bh[2];
                ldsm2(bh[0], bh[1], sbase + offb);
                mma_fp16(acc[jn], ah, bh);
            }
        }
    }
    int er = lane >> 2, ec = (lane & 3) * 2;
#pragma unroll
    for (int jn = 0; jn < 2; jn++) {
        int row = bm + wid * 16 + er;
        int col = jn * 8 + ec;
        *(float2*)(g_t16 + (size_t)row * GG + col) = make_float2(acc[jn][0], acc[jn][1]);
        *(float2*)(g_t16 + (size_t)(row + 8) * GG + col) = make_float2(acc[jn][2], acc[jn][3]);
    }
}

// ======================= attention pass A (ldsm.trans, uint4 loads) ======
#define O_QH 0
#define O_KH 9216
#define O_VN 18432
#define O_KW 27648
#define O_AH 36864
#define O_END 54272
#define RQ 72
#define RT 136

__global__ __launch_bounds__(256, 2) void attn_intra_k(const float* __restrict__ lam) {
    extern __shared__ __align__(16) __half sh16[];
    float* dtab = (float*)(sh16 + O_END);
    uint32_t sbase = smem_u32(sh16);

    int tid = threadIdx.x, wid = tid >> 5, lane = tid & 31;
    int wm = wid & 1, wn = wid >> 1;
    int chunk = blockIdx.x, bh = blockIdx.y;
    int b = bh / HH, h = bh % HH;
    float lambda = lam[h];
    int n0 = chunk * CC;

    for (int i = tid; i <= CC; i += 256) dtab[i] = __expf(lambda * (float)i);

    for (int i = tid; i < 1024; i += 256) {
        int p = i >> 3, d8 = (i & 7) * 8;
        size_t gb = (size_t)(b * NSEQ + n0 + p) * EE + h * DD + d8;
        uint4 qv = *(const uint4*)(g_q16 + gb);
        uint4 kv = *(const uint4*)(g_k16 + gb);
        uint4 vv = *(const uint4*)(g_v16 + gb);
        *(uint4*)(sh16 + O_QH + p * RQ + d8) = qv;
        *(uint4*)(sh16 + O_KH + p * RQ + d8) = kv;
        *(uint4*)(sh16 + O_VN + p * RQ + d8) = vv;
        float w = __expf(lambda * (float)(CC - p));
        __half* kp = (__half*)&kv;
        __align__(16) __half kw[8];
#pragma unroll
        for (int e = 0; e < 8; e++)
            kw[e] = __float2half(__half2float(kp[e]) * w);
        *(uint4*)(sh16 + O_KW + p * RQ + d8) = *(uint4*)kw;
    }
    __syncthreads();

    int a_r = lane & 15, a_k = (lane >> 4) << 3;
    int b_r = lane & 7, b_k = ((lane >> 3) & 1) << 3;
    int er = lane >> 2, ec = (lane & 3) * 2;
    int tb_k = lane & 15;
    int ta_k = (lane & 7) | ((lane >> 4) << 3);
    int ta_m = ((lane >> 3) & 1) << 3;

    // ---- phase 1: S = Q @ K^T ----
    {
        float accS[4][4][4];
#pragma unroll
        for (int i = 0; i < 4; i++)
#pragma unroll
            for (int j = 0; j < 4; j++)
#pragma unroll
                for (int e = 0; e < 4; e++) accS[i][j][e] = 0.f;

#pragma unroll
        for (int ks = 0; ks < 4; ks++) {
            int kk = ks * 16;
            uint32_t kh[4][2];
#pragma unroll
            for (int jn = 0; jn < 4; jn++) {
                int nrow = wn * 32 + jn * 8 + b_r;
                ldsm2(kh[jn][0], kh[jn][1],
                      sbase + (uint32_t)(O_KH + nrow * RQ + kk + b_k) * 2);
            }
#pragma unroll
            for (int im = 0; im < 4; im++) {
                int row = wm * 64 + im * 16 + a_r;
                uint32_t qh[4];
                ldsm4(qh[0], qh[1], qh[2], qh[3],
                      sbase + (uint32_t)(O_QH + row * RQ + kk + a_k) * 2);
#pragma unroll
                for (int jn = 0; jn < 4; jn++)
                    mma_fp16(accS[im][jn], qh, kh[jn]);
            }
        }
#pragma unroll
        for (int im = 0; im < 4; im++)
#pragma unroll
            for (int jn = 0; jn < 4; jn++) {
                int p0 = wm * 64 + im * 16 + er;
                int j0 = wn * 32 + jn * 8 + ec;
                int dj = p0 - j0;
                float v0 = (dj >= 0)     ? accS[im][jn][0] * dtab[dj] : 0.f;
                float v1 = (dj - 1 >= 0) ? accS[im][jn][1] * dtab[dj - 1] : 0.f;
                float v2 = (dj + 8 >= 0) ? accS[im][jn][2] * dtab[dj + 8] : 0.f;
                float v3 = (dj + 7 >= 0) ? accS[im][jn][3] * dtab[dj + 7] : 0.f;
                *(uint32_t*)(sh16 + O_AH + p0 * RT + j0) = pack2h(v0, v1);
                *(uint32_t*)(sh16 + O_AH + (p0 + 8) * RT + j0) = pack2h(v2, v3);
            }
    }
    __syncthreads();

    // ---- phase 2: O = A @ V (V^T via ldsm2t) -> g_attn16 ----
    {
        float accO[4][2][4];
#pragma unroll
        for (int i = 0; i < 4; i++)
#pragma unroll
            for (int j = 0; j < 2; j++)
#pragma unroll
                for (int e = 0; e < 4; e++) accO[i][j][e] = 0.f;

#pragma unroll
        for (int ks = 0; ks < 8; ks++) {
            int kk = ks * 16;
            uint32_t vh[2][2];
#pragma unroll
            for (int jn = 0; jn < 2; jn++) {
                int ncol = wn * 16 + jn * 8;
                ldsm2t(vh[jn][0], vh[jn][1],
                       sbase + (uint32_t)(O_VN + (kk + tb_k) * RQ + ncol) * 2);
            }
#pragma unroll
            for (int im = 0; im < 4; im++) {
                int row = wm * 64 + im * 16 + a_r;
                uint32_t ah[4];
                ldsm4(ah[0], ah[1], ah[2], ah[3],
                      sbase + (uint32_t)(O_AH + row * RT + kk + a_k) * 2);
#pragma unroll
                for (int jn = 0; jn < 2; jn++)
                    mma_fp16(accO[im][jn], ah, vh[jn]);
            }
        }
#pragma unroll
        for (int im = 0; im < 4; im++)
#pragma unroll
            for (int jn = 0; jn < 2; jn++) {
                int p0 = wm * 64 + im * 16 + er;
                int col = wn * 16 + jn * 8 + ec;
                size_t gb = (size_t)(b * NSEQ + n0 + p0) * EE + h * DD + col;
                *(uint32_t*)(g_attn16 + gb) = pack2h(accO[im][jn][0], accO[im][jn][1]);
                *(uint32_t*)(g_attn16 + gb + (size_t)8 * EE) =
                    pack2h(accO[im][jn][2], accO[im][jn][3]);
            }
    }

    // ---- phase 3: T = Kw^T @ V ----
    {
        float accT[2][2][4];
#pragma unroll
        for (int i = 0; i < 2; i++)
#pragma unroll
            for (int j = 0; j < 2; j++)
#pragma unroll
                for (int e = 0; e < 4; e++) accT[i][j][e] = 0.f;

#pragma unroll
        for (int ks = 0; ks < 8; ks++) {
            int kk = ks * 16;
            uint32_t vh[2][2];
#pragma unroll
            for (int jn = 0; jn < 2; jn++) {
                int ncol = wn * 16 + jn * 8;
                ldsm2t(vh[jn][0], vh[jn][1],
                       sbase + (uint32_t)(O_VN + (kk + tb_k) * RQ + ncol) * 2);
            }
#pragma unroll
            for (int im = 0; im < 2; im++) {
                int mcol = wm * 32 + im * 16;
                uint32_t kwh[4];
                ldsm4t(kwh[0], kwh[1], kwh[2], kwh[3],
                       sbase + (uint32_t)(O_KW + (kk + ta_k) * RQ + mcol + ta_m) * 2);
#pragma unroll
                for (int jn = 0; jn < 2; jn++)
                    mma_fp16(accT[im][jn], kwh, vh[jn]);
            }
        }
        size_t tb = ((size_t)bh * NCH + chunk) * DD * DD;
#pragma unroll
        for (int im = 0; im < 2; im++)
#pragma unroll
            for (int jn = 0; jn < 2; jn++) {
                int dk = wm * 32 + im * 16 + er;
                int dv = wn * 16 + jn * 8 + ec;
                *(float2*)(g_T + tb + dk * DD + dv) =
                    make_float2(accT[im][jn][0], accT[im][jn][1]);
                *(float2*)(g_T + tb + (dk + 8) * DD + dv) =
                    make_float2(accT[im][jn][2], accT[im][jn][3]);
            }
    }
}

// ======================= pass B: chunk-state scan (MLP-16) ===============
__global__ __launch_bounds__(256) void scan_k(const float* __restrict__ lam) {
    int idx = blockIdx.x * 256 + threadIdx.x;
    int bh = idx >> 12;
    int e = idx & 4095;
    int h = bh % HH;
    float gamma = __expf(lam[h] * (float)CC);
    size_t base = (size_t)bh * NCH * DD * DD + e;

    // batch all 16 loads (address-independent) for full MLP
    float tv[NCH];
#pragma unroll
    for (int t = 0; t < NCH; t++) tv[t] = g_T[base + t * DD * DD];

    float s = 0.f;
#pragma unroll
    for (int t = 0; t < NCH; t++) {
        g_S[base + t * DD * DD] = s;
        s = gamma * s + tv[t];
    }
}

// ======================= pass C: inter (mma) + gate fuse + fp16 out ======
#define I_QE 0
#define I_ST 9216
#define I_END 13824

__global__ __launch_bounds__(256) void attn_inter_k(const float* __restrict__ lam,
                                                    const float* __restrict__ Wg2) {
    extern __shared__ __align__(16) __half si16[];
    float* fb = (float*)(si16 + I_END);
    float* t16s = fb;
    float* wg2s = fb + 2048;
    uint32_t sbase = smem_u32(si16);

    int tid = threadIdx.x, wid = tid >> 5, lane = tid & 31;
    int wm = wid & 1, wn = wid >> 1;
    int chunk = blockIdx.x, bh = blockIdx.y;
    int b = bh / HH, h = bh % HH;
    float lambda = lam[h];
    int n0 = chunk * CC;

    for (int i = tid; i < 1024; i += 256) {
        int p = i >> 3, d8 = (i & 7) * 8;
        size_t gb = (size_t)(b * NSEQ + n0 + p) * EE + h * DD + d8;
        uint4 qv = *(const uint4*)(g_q16 + gb);
        float w = __expf(lambda * (float)p);
        __half* qp = (__half*)&qv;
        __align__(16) __half qe[8];
#pragma unroll
        for (int e = 0; e < 8; e++)
            qe[e] = __float2half(__half2float(qp[e]) * w);
        *(uint4*)(si16 + I_QE + p * RQ + d8) = *(uint4*)qe;
    }
    size_t sbo = ((size_t)bh * NCH + chunk) * DD * DD;
    for (int i = tid; i < 1024; i += 256) {
        int dk = i >> 4, dv4 = (i & 15) * 4;
        float4 sv = *(const float4*)(g_S + sbo + dk * 64 + dv4);
        uint2 u;
        u.x = pack2h(sv.x, sv.y);
        u.y = pack2h(sv.z, sv.w);
        *(uint2*)(si16 + I_ST + dk * RQ + dv4) = u;
    }
    for (int i = tid; i < 512; i += 256)
        *(float4*)(t16s + i * 4) =
            *(const float4*)(g_t16 + (size_t)(b * NSEQ + n0) * GG + i * 4);
    for (int i = tid; i < 256; i += 256) {
        int g = i >> 4, c4 = (i & 15) * 4;
        *(float4*)(wg2s + g * 64 + c4) = *(const float4*)(Wg2 + g * EE + h * DD + c4);
    }
    __syncthreads();

    int a_r = lane & 15, a_k = (lane >> 4) << 3;
    int er = lane >> 2, ec = (lane & 3) * 2;
    int tb_k = lane & 15;

    float accO[4][2][4];
#pragma unroll
    for (int i = 0; i < 4; i++)
#pragma unroll
        for (int j = 0; j < 2; j++)
#pragma unroll
            for (int e = 0; e < 4; e++) accO[i][j][e] = 0.f;

#pragma unroll
    for (int ks = 0; ks < 4; ks++) {
        int kk = ks * 16;
        uint32_t shh[2][2];
#pragma unroll
        for (int jn = 0; jn < 2; jn++) {
            int ncol = wn * 16 + jn * 8;
            ldsm2t(shh[jn][0], shh[jn][1],
                   sbase + (uint32_t)(I_ST + (kk + tb_k) * RQ + ncol) * 2);
        }
#pragma unroll
        for (int im = 0; im < 4; im++) {
            int row = wm * 64 + im * 16 + a_r;
            uint32_t qh[4];
            ldsm4(qh[0], qh[1], qh[2], qh[3],
                  sbase + (uint32_t)(I_QE + row * RQ + kk + a_k) * 2);
#pragma unroll
            for (int jn = 0; jn < 2; jn++)
                mma_fp16(accO[im][jn], qh, shh[jn]);
        }
    }

#pragma unroll
    for (int im = 0; im < 4; im++)
#pragma unroll
        for (int jn = 0; jn < 2; jn++) {
            int p0 = wm * 64 + im * 16 + er;
            int col = wn * 16 + jn * 8 + ec;
#pragma unroll
            for (int rr = 0; rr < 2; rr++) {
                int p = p0 + rr * 8;
                size_t gb = (size_t)(b * NSEQ + n0 + p) * EE + h * DD + col;
                uint32_t aw = *(const uint32_t*)(g_attn16 + gb);
                __half* ap = (__half*)&aw;
                float s0 = 0.f, s1 = 0.f;
#pragma unroll
                for (int g = 0; g < 16; g++) {
                    float tv = t16s[p * 16 + g];
                    s0 += tv * wg2s[g * 64 + col];
                    s1 += tv * wg2s[g * 64 + col + 1];
                }
                float g0 = 1.f / (1.f + __expf(-s0));
                float g1 = 1.f / (1.f + __expf(-s1));
                float v0 = (__half2float(ap[0]) + accO[im][jn][rr * 2 + 0]) * g0;
                float v1 = (__half2float(ap[1]) + accO[im][jn][rr * 2 + 1]) * g1;
                *(uint32_t*)(g_ah + gb) = pack2h(v0, v1);
            }
        }
}

// ======================= LayerNorm (fp16 input) ==========================
__global__ __launch_bounds__(256) void ln_k(const float* __restrict__ w,
                                            const float* __restrict__ bias,
                                            float* __restrict__ out) {
    int row = blockIdx.x;
    int t = threadIdx.x;
    const __half* yr = g_y16 + (size_t)row * EE;
    float v0 = __half2float(yr[t]);
    float v1 = __half2float(yr[t + 256]);
    float v2 = __half2float(yr[t + 512]);

    __shared__ float red[32];
    float s = v0 + v1 + v2;
#pragma unroll
    for (int off = 16; off > 0; off >>= 1) s += __shfl_down_sync(0xffffffffu, s, off);
    if ((t & 31) == 0) red[t >> 5] = s;
    __syncthreads();
    if (t < 32) {
        float x = (t < 8) ? red[t] : 0.f;
#pragma unroll
        for (int off = 4; off > 0; off >>= 1) x += __shfl_down_sync(0xffffffffu, x, off);
        if (t == 0) red[0] = x;
    }
    __syncthreads();
    float mu = red[0] * (1.f / 768.f);
    __syncthreads();

    float d0 = v0 - mu, d1 = v1 - mu, d2 = v2 - mu;
    float s2 = d0 * d0 + d1 * d1 + d2 * d2;
#pragma unroll
    for (int off = 16; off > 0; off >>= 1) s2 += __shfl_down_sync(0xffffffffu, s2, off);
    if ((t & 31) == 0) red[t >> 5] = s2;
    __syncthreads();
    if (t < 32) {
        float x = (t < 8) ? red[t] : 0.f;
#pragma unroll
        for (int off = 4; off > 0; off >>= 1) x += __shfl_down_sync(0xffffffffu, x, off);
        if (t == 0) red[0] = x;
    }
    __syncthreads();
    float var = red[0] * (1.f / 768.f);
    float rs = rsqrtf(var + 1e-5f);

    size_t ob = (size_t)row * EE;
    out[ob + t]       = d0 * rs * w[t]       + bias[t];
    out[ob + t + 256] = d1 * rs * w[t + 256] + bias[t + 256];
    out[ob + t + 512] = d2 * rs * w[t + 512] + bias[t + 512];
}

// =========================================================================
extern "C" void kernel_launch(void* const* d_in, const int* in_sizes, int n_in,
                              void* d_out, int out_size) {
    (void)in_sizes; (void)n_in; (void)out_size;
    const float* x         = (const float*)d_in[0];
    const float* log_slope = (const float*)d_in[1];
    const float* Wq        = (const float*)d_in[2];
    const float* Wk        = (const float*)d_in[3];
    const float* Wv        = (const float*)d_in[4];
    const float* Wo        = (const float*)d_in[5];
    const float* Wg1       = (const float*)d_in[6];
    const float* Wg2       = (const float*)d_in[7];
    const float* ln_w      = (const float*)d_in[8];
    const float* ln_b      = (const float*)d_in[9];
    float* out = (float*)d_out;

    int smMM = 3 * MMSTG;
    cudaFuncSetAttribute(mm_tc, cudaFuncAttributeMaxDynamicSharedMemorySize, smMM);
    int smM2 = 3 * M2STG;
    cudaFuncSetAttribute(mm_tc2, cudaFuncAttributeMaxDynamicSharedMemorySize, smM2);
    int smA = O_END * 2 + 132 * 4;
    cudaFuncSetAttribute(attn_intra_k, cudaFuncAttributeMaxDynamicSharedMemorySize, smA);
    int smG1 = (12416 + 32 * 72) * 2;
    cudaFuncSetAttribute(mm_g1, cudaFuncAttributeMaxDynamicSharedMemorySize, smG1);
    int smC = I_END * 2 + (2048 + 1024) * 4;
    cudaFuncSetAttribute(attn_inter_k, cudaFuncAttributeMaxDynamicSharedMemorySize, smC);

    prep_k<<<5424, 256>>>(x, Wq, Wk, Wv, Wo, Wg1);
    mm_tc<<<dim3(EE / 128, MTOT / 128, 3), 256, smMM>>>();
    mm_g1<<<MTOT / 32, 64, smG1>>>();
    attn_intra_k<<<dim3(NCH, BHH), 256, smA>>>(log_slope);
    scan_k<<<BHH * NCH * 16 * 16 / 256, 256>>>(log_slope);
    attn_inter_k<<<dim3(NCH, BHH), 256, smC>>>(log_slope, Wg2);
    mm_tc2<<<dim3(EE / 128, MTOT / 64, 1), 256, smM2>>>();
    ln_k<<<MTOT, 256>>>(ln_w, ln_b, out);
}